// round 16
// baseline (speedup 1.0000x reference)
#include <cuda_runtime.h>
#include <cuda_fp16.h>
#include <math.h>
#include <stdint.h>

// Problem constants
#define Bsz    8
#define Tlen   1024
#define EMB    1024
#define NHEADS 16
#define HD     64

#define MTOT (Bsz * Tlen)          // 8192 rows

// ---------------------------------------------------------------------------
// Scratch (device globals — allocation-free per harness rules).
// Pure fp16 operands everywhere; fp32 accumulation in MMA.
// ---------------------------------------------------------------------------
__device__ __half g_x1[MTOT * EMB];
__device__ __half g_q1[MTOT * EMB];
__device__ __half g_k1[MTOT * EMB];
__device__ __half g_v1[MTOT * EMB];
__device__ __half g_a1[MTOT * EMB];
__device__ __half g_wq1[EMB * EMB], g_wk1[EMB * EMB];
__device__ __half g_wv1[EMB * EMB], g_wo1[EMB * EMB];

// ---------------------------------------------------------------------------
// Warp MMA helpers (mma.sync + ldmatrix — plain sm_103 features only)
// ---------------------------------------------------------------------------
__device__ __forceinline__ uint32_t smem_u32(const void* p) {
    uint32_t a;
    asm("{ .reg .u64 t; cvta.to.shared.u64 t, %1; cvt.u32.u64 %0, t; }"
        : "=r"(a) : "l"(p));
    return a;
}

__device__ __forceinline__ void ldsm_x4(uint32_t& r0, uint32_t& r1,
                                        uint32_t& r2, uint32_t& r3, uint32_t a) {
    asm volatile("ldmatrix.sync.aligned.m8n8.x4.shared.b16 {%0,%1,%2,%3}, [%4];"
                 : "=r"(r0), "=r"(r1), "=r"(r2), "=r"(r3) : "r"(a));
}
__device__ __forceinline__ void ldsm_x4_t(uint32_t* r, uint32_t a) {
    asm volatile("ldmatrix.sync.aligned.m8n8.x4.trans.shared.b16 {%0,%1,%2,%3}, [%4];"
                 : "=r"(r[0]), "=r"(r[1]), "=r"(r[2]), "=r"(r[3]) : "r"(a));
}
__device__ __forceinline__ void ldsm_x2(uint32_t& r0, uint32_t& r1, uint32_t a) {
    asm volatile("ldmatrix.sync.aligned.m8n8.x2.shared.b16 {%0,%1}, [%2];"
                 : "=r"(r0), "=r"(r1) : "r"(a));
}

__device__ __forceinline__ void mma16816(float* c, const uint32_t* a,
                                         const uint32_t* b) {
    asm volatile(
        "mma.sync.aligned.m16n8k16.row.col.f32.f16.f16.f32 "
        "{%0,%1,%2,%3}, {%4,%5,%6,%7}, {%8,%9}, {%0,%1,%2,%3};"
        : "+f"(c[0]), "+f"(c[1]), "+f"(c[2]), "+f"(c[3])
        : "r"(a[0]), "r"(a[1]), "r"(a[2]), "r"(a[3]), "r"(b[0]), "r"(b[1]));
}

__device__ __forceinline__ uint32_t pack2(float a, float b) {
    __half2 p; p.x = __float2half(a); p.y = __float2half(b);
    return *(uint32_t*)&p;
}

// ---------------------------------------------------------------------------
// Merged fp32 -> fp16 conversion: x (8192 blocks) + 4 weights (1024 each).
// One launch removes four small-kernel latency floors.
// ---------------------------------------------------------------------------
__global__ __launch_bounds__(256)
void cvt_all(const float* __restrict__ x,
             const float* __restrict__ wq, const float* __restrict__ wk,
             const float* __restrict__ wv, const float* __restrict__ wo,
             __half* __restrict__ x1,
             __half* __restrict__ wq1, __half* __restrict__ wk1,
             __half* __restrict__ wv1, __half* __restrict__ wo1)
{
    const int bid = blockIdx.x;
    const float* s;
    __half* d;
    int base;
    if (bid < 8192) {
        s = x; d = x1; base = bid * 1024;
    } else {
        const int w = (bid - 8192) >> 10;
        s = (w == 0) ? wq : (w == 1) ? wk : (w == 2) ? wv : wo;
        d = (w == 0) ? wq1 : (w == 1) ? wk1 : (w == 2) ? wv1 : wo1;
        base = ((bid - 8192) & 1023) * 1024;
    }
    const int i = base + threadIdx.x * 4;
    float4 v = *(const float4*)(s + i);
    *(__half2*)(d + i)     = __floats2half2_rn(v.x, v.y);
    *(__half2*)(d + i + 2) = __floats2half2_rn(v.z, v.w);
}

// ---------------------------------------------------------------------------
// fp16 tensor GEMM (verified R15 core): C tile 128x128 of
// A[M,1024]*B[N,1024]^T + bias. fp32 accumulate, double-buffered smem.
// ---------------------------------------------------------------------------
#define TCK   32
#define NCHK  (EMB / TCK)
#define TLD   40
#define TILE_B (128 * TLD * 2)
#define BUF_B  (2 * TILE_B)
#define SMEM_MMA (2 * BUF_B)        // 40960 B

__device__ __forceinline__
void ld_chunk(uint4* v, const __half* A0, const __half* B0,
              int row, int col, int kc)
{
    const size_t off = (size_t)row * EMB + kc + col;
    v[0] = *(const uint4*)(A0 + off); v[1] = *(const uint4*)(A0 + off + 8);
    v[2] = *(const uint4*)(B0 + off); v[3] = *(const uint4*)(B0 + off + 8);
}

__device__ __forceinline__
void st_chunk(char* smbuf, const uint4* v, int row, int col)
{
    const uint32_t off = (uint32_t)(row * TLD + col) * 2;
    *(uint4*)(smbuf + 0 * TILE_B + off)      = v[0];
    *(uint4*)(smbuf + 0 * TILE_B + off + 16) = v[1];
    *(uint4*)(smbuf + 1 * TILE_B + off)      = v[2];
    *(uint4*)(smbuf + 1 * TILE_B + off + 16) = v[3];
}

__device__ __forceinline__
void gemm_mma_body(const __half* __restrict__ a1, const __half* __restrict__ b1,
                   const float* __restrict__ bias,
                   float* __restrict__ C, __half* __restrict__ Ch,
                   int mBase, int nBase)
{
    extern __shared__ char sm[];
    const uint32_t smb = smem_u32(sm);

    const int tid  = threadIdx.x;
    const int wid  = tid >> 5;
    const int lane = tid & 31;
    const int wm = (wid >> 2) * 64;
    const int wn = (wid & 3) * 32;

    const int grow = tid >> 1;
    const int gcol = (tid & 1) * 16;

    const __half* A0 = a1 + (size_t)mBase * EMB;
    const __half* B0 = b1 + (size_t)nBase * EMB;

    const uint32_t aRow = wm + (lane & 15);
    const uint32_t aK   = (lane >> 4) * 8;
    const uint32_t bRow = wn + (lane & 7);
    const uint32_t bK   = ((lane >> 3) & 1) * 8;

    float acc[4][4][4];
#pragma unroll
    for (int mi = 0; mi < 4; mi++)
#pragma unroll
        for (int ni = 0; ni < 4; ni++)
#pragma unroll
            for (int e = 0; e < 4; e++) acc[mi][ni][e] = 0.f;

    {
        uint4 v[4];
        ld_chunk(v, A0, B0, grow, gcol, 0);
        st_chunk(sm, v, grow, gcol);
    }
    __syncthreads();

    int buf = 0;
    for (int c = 0; c < NCHK; c++) {
        const bool more = (c + 1) < NCHK;
        uint4 pf[4];
        if (more) ld_chunk(pf, A0, B0, grow, gcol, (c + 1) * TCK);

        const uint32_t bb = smb + buf * BUF_B;
#pragma unroll
        for (int k16 = 0; k16 < 2; k16++) {
            const uint32_t kb = k16 * 16;
            uint32_t fa[4][4], fb[4][2];
#pragma unroll
            for (int mi = 0; mi < 4; mi++) {
                uint32_t ao = ((aRow + mi * 16) * TLD + kb + aK) * 2;
                ldsm_x4(fa[mi][0], fa[mi][1], fa[mi][2], fa[mi][3],
                        bb + 0 * TILE_B + ao);
            }
#pragma unroll
            for (int ni = 0; ni < 4; ni++) {
                uint32_t bo = ((bRow + ni * 8) * TLD + kb + bK) * 2;
                ldsm_x2(fb[ni][0], fb[ni][1], bb + 1 * TILE_B + bo);
            }
#pragma unroll
            for (int mi = 0; mi < 4; mi++)
#pragma unroll
                for (int ni = 0; ni < 4; ni++)
                    mma16816(acc[mi][ni], fa[mi], fb[ni]);
        }

        if (more) {
            const int nb = buf ^ 1;
            st_chunk(sm + nb * BUF_B, pf, grow, gcol);
            __syncthreads();
            buf = nb;
        }
    }

    const int tr = lane >> 2;
    const int tc = (lane & 3) * 2;
#pragma unroll
    for (int mi = 0; mi < 4; mi++) {
        const int gm0 = mBase + wm + mi * 16 + tr;
#pragma unroll
        for (int ni = 0; ni < 4; ni++) {
            const int gn = nBase + wn + ni * 8 + tc;
            const float b0 = bias[gn], b1 = bias[gn + 1];
            float v0 = acc[mi][ni][0] + b0, v1 = acc[mi][ni][1] + b1;
            float v2 = acc[mi][ni][2] + b0, v3 = acc[mi][ni][3] + b1;
            if (C) {
                *(float2*)(C + (size_t)gm0 * EMB + gn)       = make_float2(v0, v1);
                *(float2*)(C + (size_t)(gm0 + 8) * EMB + gn) = make_float2(v2, v3);
            } else {
                *(__half2*)(Ch + (size_t)gm0 * EMB + gn)       = __floats2half2_rn(v0, v1);
                *(__half2*)(Ch + (size_t)(gm0 + 8) * EMB + gn) = __floats2half2_rn(v2, v3);
            }
        }
    }
}

// Fused QKV: grid (24, 64)
__global__ __launch_bounds__(256)
void gemm_qkv_tc(const __half* __restrict__ x1,
                 const __half* __restrict__ wq1, const __half* __restrict__ wk1,
                 const __half* __restrict__ wv1,
                 const float* __restrict__ bq, const float* __restrict__ bk,
                 const float* __restrict__ bv,
                 __half* __restrict__ q1, __half* __restrict__ k1,
                 __half* __restrict__ v1)
{
    const int sel = blockIdx.x >> 3;
    const int nb  = blockIdx.x & 7;
    const __half* wh  = (sel == 0) ? wq1 : (sel == 1) ? wk1 : wv1;
    const float* bias = (sel == 0) ? bq  : (sel == 1) ? bk  : bv;
    __half* Ch        = (sel == 0) ? q1  : (sel == 1) ? k1  : v1;
    gemm_mma_body(x1, wh, bias, nullptr, Ch, blockIdx.y * 128, nb * 128);
}

// Output projection (fp32 output): grid (8, 64)
__global__ __launch_bounds__(256)
void gemm_o_tc(const __half* __restrict__ a1, const __half* __restrict__ wo1,
               const float* __restrict__ bias, float* __restrict__ C)
{
    gemm_mma_body(a1, wo1, bias, C, nullptr, blockIdx.y * 128, blockIdx.x * 128);
}

// ---------------------------------------------------------------------------
// Tensor-core flash attention, pure fp16 operands, fp32 softmax/accum.
// CTA = (q-tile 128, head, batch); 8 warps x 16 q-rows. Key tiles of 64.
// K/V double-buffered: global->reg prefetch before the MMA block, store to
// the alternate stage after, ONE __syncthreads per iteration.
// Mask: only the diagonal 64-chunk tile, upper-triangular.
// ---------------------------------------------------------------------------
#define LDT 72
#define QH0 0
#define KH0 (128 * LDT)
#define KVST (2 * 64 * LDT)          // one K+V stage (halves)
#define ATT_SMEM ((128 * LDT + 2 * KVST) * 2)   // 55,296 B

__global__ __launch_bounds__(256)
void attn_mma(const __half* __restrict__ q1, const __half* __restrict__ k1,
              const __half* __restrict__ v1, const float* __restrict__ scale_p,
              __half* __restrict__ o1)
{
    extern __shared__ char smc[];
    __half* sb = (__half*)smc;
    const uint32_t smb = smem_u32(smc);

    const int tid = threadIdx.x, wid = tid >> 5, lane = tid & 31;
    const int wq = wid * 16;
    const int qt = blockIdx.x, h = blockIdx.y, b = blockIdx.z;
    const float scale = scale_p[0];
    const int tr  = lane >> 2;
    const int tc2 = 2 * (lane & 3);

    // K/V loader mapping: r = key row 0..63, c = 16-half chunk
    const int rkv = tid >> 2;
    const int ckv = (tid & 3) * 16;

    // ---- load Q tile ----
    {
        const int r = tid >> 1, c = (tid & 1) * 32;
        const size_t go = ((size_t)(b * Tlen + qt * 128 + r)) * EMB + h * HD + c;
        const uint4* s0 = (const uint4*)(q1 + go);
        uint4* d0 = (uint4*)(sb + QH0 + r * LDT + c);
#pragma unroll
        for (int j = 0; j < 4; j++) d0[j] = s0[j];
    }

    // ---- preload K/V stage 0 ----
    {
        const size_t go = ((size_t)(b * Tlen + rkv)) * EMB + h * HD + ckv;
        uint4 v0[4];
        v0[0] = ((const uint4*)(k1 + go))[0];
        v0[1] = ((const uint4*)(k1 + go))[1];
        v0[2] = ((const uint4*)(v1 + go))[0];
        v0[3] = ((const uint4*)(v1 + go))[1];
        uint4* dk = (uint4*)(sb + KH0 + rkv * LDT + ckv);
        uint4* dv = (uint4*)(sb + KH0 + 64 * LDT + rkv * LDT + ckv);
        dk[0] = v0[0]; dk[1] = v0[1]; dv[0] = v0[2]; dv[1] = v0[3];
    }
    __syncthreads();

    // ---- Q A-frags, hoisted ----
    uint32_t fq[4][4];
    {
        const uint32_t arow = wq + (lane & 15);
        const uint32_t akk  = (lane >> 4) * 8;
#pragma unroll
        for (int ks = 0; ks < 4; ks++)
            ldsm_x4(fq[ks][0], fq[ks][1], fq[ks][2], fq[ks][3],
                    smb + (QH0 + arow * LDT + ks * 16 + akk) * 2);
    }

    float m0 = -INFINITY, m1 = -INFINITY, l0 = 0.f, l1 = 0.f;
    float o[8][4];
#pragma unroll
    for (int nd = 0; nd < 8; nd++)
#pragma unroll
        for (int e = 0; e < 4; e++) o[nd][e] = 0.f;

    const int ktd  = qt * 2 + (wid >> 2);
    const int rel0 = (wid & 3) * 16 + tr;

    int buf = 0;
    for (int kt = 0; kt < 16; kt++) {
        // prefetch next K/V tile into registers
        uint4 pf[4];
        const bool more = (kt + 1) < 16;
        if (more) {
            const size_t go = ((size_t)(b * Tlen + (kt + 1) * 64 + rkv)) * EMB
                            + h * HD + ckv;
            pf[0] = ((const uint4*)(k1 + go))[0];
            pf[1] = ((const uint4*)(k1 + go))[1];
            pf[2] = ((const uint4*)(v1 + go))[0];
            pf[3] = ((const uint4*)(v1 + go))[1];
        }

        const uint32_t kbs = KH0 + buf * KVST;            // K stage base (halves)
        const uint32_t vbs = kbs + 64 * LDT;              // V stage base

        // ---- S = Q.K^T ----
        float s[8][4];
#pragma unroll
        for (int ni = 0; ni < 8; ni++)
#pragma unroll
            for (int e = 0; e < 4; e++) s[ni][e] = 0.f;

#pragma unroll
        for (int ni = 0; ni < 8; ni += 2) {
#pragma unroll
            for (int ks = 0; ks < 4; ks++) {
                uint32_t kh4[4];
                const uint32_t boff =
                    ((ni + (lane >> 4)) * 8 + (lane & 7)) * LDT
                    + ks * 16 + ((lane >> 3) & 1) * 8;
                ldsm_x4(kh4[0], kh4[1], kh4[2], kh4[3], smb + (kbs + boff) * 2);
                mma16816(s[ni],     fq[ks], kh4);
                mma16816(s[ni + 1], fq[ks], kh4 + 2);
            }
        }

        // scale + mask (diagonal chunk tile only)
#pragma unroll
        for (int ni = 0; ni < 8; ni++)
#pragma unroll
            for (int e = 0; e < 4; e++) s[ni][e] *= scale;
        if (kt == ktd) {
#pragma unroll
            for (int ni = 0; ni < 8; ni++) {
                const int c0 = ni * 8 + tc2;
                if (c0     > rel0)     s[ni][0] = -INFINITY;
                if (c0 + 1 > rel0)     s[ni][1] = -INFINITY;
                if (c0     > rel0 + 8) s[ni][2] = -INFINITY;
                if (c0 + 1 > rel0 + 8) s[ni][3] = -INFINITY;
            }
        }

        // ---- online softmax (rows tr and tr+8) ----
        float tm0 = -INFINITY, tm1 = -INFINITY;
#pragma unroll
        for (int ni = 0; ni < 8; ni++) {
            tm0 = fmaxf(tm0, fmaxf(s[ni][0], s[ni][1]));
            tm1 = fmaxf(tm1, fmaxf(s[ni][2], s[ni][3]));
        }
        tm0 = fmaxf(tm0, __shfl_xor_sync(0xffffffffu, tm0, 1));
        tm0 = fmaxf(tm0, __shfl_xor_sync(0xffffffffu, tm0, 2));
        tm1 = fmaxf(tm1, __shfl_xor_sync(0xffffffffu, tm1, 1));
        tm1 = fmaxf(tm1, __shfl_xor_sync(0xffffffffu, tm1, 2));
        const float mn0 = fmaxf(m0, tm0), mn1 = fmaxf(m1, tm1);
        const float co0 = __expf(m0 - mn0), co1 = __expf(m1 - mn1);

        float ts0 = 0.f, ts1 = 0.f;
#pragma unroll
        for (int ni = 0; ni < 8; ni++) {
            s[ni][0] = __expf(s[ni][0] - mn0); ts0 += s[ni][0];
            s[ni][1] = __expf(s[ni][1] - mn0); ts0 += s[ni][1];
            s[ni][2] = __expf(s[ni][2] - mn1); ts1 += s[ni][2];
            s[ni][3] = __expf(s[ni][3] - mn1); ts1 += s[ni][3];
        }
        ts0 += __shfl_xor_sync(0xffffffffu, ts0, 1);
        ts0 += __shfl_xor_sync(0xffffffffu, ts0, 2);
        ts1 += __shfl_xor_sync(0xffffffffu, ts1, 1);
        ts1 += __shfl_xor_sync(0xffffffffu, ts1, 2);
        l0 = l0 * co0 + ts0; l1 = l1 * co1 + ts1;
        m0 = mn0; m1 = mn1;
#pragma unroll
        for (int nd = 0; nd < 8; nd++) {
            o[nd][0] *= co0; o[nd][1] *= co0;
            o[nd][2] *= co1; o[nd][3] *= co1;
        }

        // ---- O += P.V (P packed to fp16; V via ldmatrix.trans) ----
#pragma unroll
        for (int kp = 0; kp < 4; kp++) {
            uint32_t fp[4];
            fp[0] = pack2(s[2 * kp][0],     s[2 * kp][1]);
            fp[1] = pack2(s[2 * kp][2],     s[2 * kp][3]);
            fp[2] = pack2(s[2 * kp + 1][0], s[2 * kp + 1][1]);
            fp[3] = pack2(s[2 * kp + 1][2], s[2 * kp + 1][3]);
#pragma unroll
            for (int nd = 0; nd < 8; nd += 2) {
                uint32_t fv[4];
                const uint32_t voff =
                    (kp * 16 + (lane & 15)) * LDT + (nd + (lane >> 4)) * 8;
                ldsm_x4_t(fv, smb + (vbs + voff) * 2);
                mma16816(o[nd],     fp, fv);
                mma16816(o[nd + 1], fp, fv + 2);
            }
        }

        // store the prefetched tile into the alternate stage; one sync/iter
        if (more) {
            const uint32_t nbs = KH0 + (buf ^ 1) * KVST;
            uint4* dk = (uint4*)(sb + nbs + rkv * LDT + ckv);
            uint4* dv = (uint4*)(sb + nbs + 64 * LDT + rkv * LDT + ckv);
            dk[0] = pf[0]; dk[1] = pf[1]; dv[0] = pf[2]; dv[1] = pf[3];
            __syncthreads();
            buf ^= 1;
        }
    }

    // ---- finalize: normalize, store fp16 ----
    const float i0 = 1.f / l0, i1 = 1.f / l1;
    const size_t row0 = (size_t)(b * Tlen + qt * 128 + wq + tr);
#pragma unroll
    for (int nd = 0; nd < 8; nd++) {
        const int col = h * HD + nd * 8 + tc2;
        *(__half2*)(o1 + row0 * EMB + col) =
            __floats2half2_rn(o[nd][0] * i0, o[nd][1] * i0);
        *(__half2*)(o1 + (row0 + 8) * EMB + col) =
            __floats2half2_rn(o[nd][2] * i1, o[nd][3] * i1);
    }
}

// ---------------------------------------------------------------------------
// Launch
// ---------------------------------------------------------------------------
extern "C" void kernel_launch(void* const* d_in, const int* in_sizes, int n_in,
                              void* d_out, int out_size)
{
    const float* x     = (const float*)d_in[0];
    const float* Wq    = (const float*)d_in[1];
    const float* bq    = (const float*)d_in[2];
    const float* Wk    = (const float*)d_in[3];
    const float* bk    = (const float*)d_in[4];
    const float* Wv    = (const float*)d_in[5];
    const float* bv    = (const float*)d_in[6];
    const float* Wo    = (const float*)d_in[7];
    const float* bo    = (const float*)d_in[8];
    const float* ascl  = (const float*)d_in[9];
    float* out = (float*)d_out;

    __half *x1, *q1, *k1, *v1, *a1, *wq1, *wk1, *wv1, *wo1;
    cudaGetSymbolAddress((void**)&x1, g_x1);
    cudaGetSymbolAddress((void**)&q1, g_q1);
    cudaGetSymbolAddress((void**)&k1, g_k1);
    cudaGetSymbolAddress((void**)&v1, g_v1);
    cudaGetSymbolAddress((void**)&a1, g_a1);
    cudaGetSymbolAddress((void**)&wq1, g_wq1);
    cudaGetSymbolAddress((void**)&wk1, g_wk1);
    cudaGetSymbolAddress((void**)&wv1, g_wv1);
    cudaGetSymbolAddress((void**)&wo1, g_wo1);

    // one merged conversion pass: x + 4 weights (12288 blocks)
    cvt_all<<<12288, 256>>>(x, Wq, Wk, Wv, Wo, x1, wq1, wk1, wv1, wo1);

    cudaFuncSetAttribute(gemm_qkv_tc, cudaFuncAttributeMaxDynamicSharedMemorySize, SMEM_MMA);
    cudaFuncSetAttribute(gemm_o_tc,   cudaFuncAttributeMaxDynamicSharedMemorySize, SMEM_MMA);
    cudaFuncSetAttribute(attn_mma,    cudaFuncAttributeMaxDynamicSharedMemorySize, ATT_SMEM);

    // QKV projections: grid (24, 64)
    dim3 qkvGrid(24, MTOT / 128);
    gemm_qkv_tc<<<qkvGrid, 256, SMEM_MMA>>>(x1, wq1, wk1, wv1,
                                            bq, bk, bv, q1, k1, v1);

    // Tensor-core attention: grid (8, 16, 8)
    dim3 agrid(Tlen / 128, NHEADS, Bsz);
    attn_mma<<<agrid, 256, ATT_SMEM>>>(q1, k1, v1, ascl, a1);

    // Output projection (fp32 out)
    dim3 ogrid(EMB / 128, MTOT / 128);
    gemm_o_tc<<<ogrid, 256, SMEM_MMA>>>(a1, wo1, bo, out);
}